// round 2
// baseline (speedup 1.0000x reference)
#include <cuda_runtime.h>
#include <math.h>

#define Bb 512
#define Nn 16
#define Cc 256
#define Kk 8192

// Scratch (device globals -- no allocations allowed)
__device__ float g_frest[Bb*Nn*Cc];   // [b][n][c] residual
__device__ float g_fhat [Bb*Nn*Cc];   // [b][n][c] accumulated quantization
__device__ float g_rest [Bb*Nn*Cc];   // pooled rows [row][c], row = b*pn+p
__device__ float g_rsq  [Bb*Nn];
__device__ float g_esq  [Kk];
__device__ unsigned long long g_best[Bb*Nn];
__device__ double g_loss;

__global__ void init_kernel(const float* __restrict__ f){
    int i = blockIdx.x*blockDim.x + threadIdx.x;
    if (i < Bb*Nn*Cc){ g_frest[i] = f[i]; g_fhat[i] = 0.0f; }
    if (i == 0) g_loss = 0.0;
}

// e_sq[k] = sum_c emb[k][c]^2, sequential FMA (match fp32 reference rounding as closely as possible)
__global__ void esq_kernel(const float* __restrict__ emb){
    int k = blockIdx.x*blockDim.x + threadIdx.x;
    if (k < Kk){
        const float* e = emb + (size_t)k*Cc;
        float acc = 0.0f;
        #pragma unroll 8
        for (int c=0;c<Cc;c++) acc = fmaf(e[c], e[c], acc);
        g_esq[k] = acc;
    }
}

// Pool over n: rest[row][c] = sum_{n in [s,e)} w * frest[b][n][c], w = 1/(e-s)
__global__ void pool_kernel(int pn){
    int row = blockIdx.x;          // 0..B*pn-1
    int c   = threadIdx.x;         // 0..255
    int b = row / pn, p = row % pn;
    int s = (p*Nn)/pn;
    int e = ((p+1)*Nn + pn - 1)/pn;   // ceil
    float w = (float)(1.0/(double)(e-s));
    float acc = 0.0f;
    for (int n=s;n<e;n++) acc = fmaf(w, g_frest[((size_t)b*Nn+n)*Cc + c], acc);
    g_rest[(size_t)row*Cc + c] = acc;
}

// rsq[row] = sum_c rest^2 (sequential FMA), plus init argmin slots
__global__ void rsq_kernel(int M){
    int row = blockIdx.x*blockDim.x + threadIdx.x;
    if (row < M){
        const float* r = g_rest + (size_t)row*Cc;
        float acc = 0.0f;
        #pragma unroll 8
        for (int c=0;c<Cc;c++) acc = fmaf(r[c], r[c], acc);
        g_rsq[row] = acc;
        g_best[row] = 0xFFFFFFFFFFFFFFFFull;
    }
}

__device__ __forceinline__ unsigned fkey(float f){
    unsigned u = __float_as_uint(f);
    return (u & 0x80000000u) ? ~u : (u | 0x80000000u);
}

// 64(rows) x 64(codes) tile, C=256 reduction, fused distance + argmin.
// Strictly sequential FMA over c per (row,code) pair.
__global__ __launch_bounds__(256) void gemm_argmin_kernel(const float* __restrict__ emb){
    __shared__ float As[32][68];
    __shared__ float Bs[32][68];
    int row0 = blockIdx.y * 64;
    int k0   = blockIdx.x * 64;
    int tid = threadIdx.x;
    int ty = tid >> 4, tx = tid & 15;

    float acc[4][4];
    #pragma unroll
    for (int i=0;i<4;i++)
        #pragma unroll
        for (int j=0;j<4;j++) acc[i][j] = 0.0f;

    int lr = tid >> 3;            // 0..31
    int lc = (tid & 7) << 2;      // 0,4,...,28

    for (int c0=0;c0<Cc;c0+=32){
        float4 a0 = *(const float4*)(g_rest + ((size_t)(row0+lr)   )*Cc + c0 + lc);
        float4 a1 = *(const float4*)(g_rest + ((size_t)(row0+lr+32))*Cc + c0 + lc);
        float4 b0 = *(const float4*)(emb    + ((size_t)(k0  +lr)   )*Cc + c0 + lc);
        float4 b1 = *(const float4*)(emb    + ((size_t)(k0  +lr+32))*Cc + c0 + lc);
        As[lc+0][lr   ]=a0.x; As[lc+1][lr   ]=a0.y; As[lc+2][lr   ]=a0.z; As[lc+3][lr   ]=a0.w;
        As[lc+0][lr+32]=a1.x; As[lc+1][lr+32]=a1.y; As[lc+2][lr+32]=a1.z; As[lc+3][lr+32]=a1.w;
        Bs[lc+0][lr   ]=b0.x; Bs[lc+1][lr   ]=b0.y; Bs[lc+2][lr   ]=b0.z; Bs[lc+3][lr   ]=b0.w;
        Bs[lc+0][lr+32]=b1.x; Bs[lc+1][lr+32]=b1.y; Bs[lc+2][lr+32]=b1.z; Bs[lc+3][lr+32]=b1.w;
        __syncthreads();
        #pragma unroll
        for (int cc=0;cc<32;cc++){
            float a[4], b[4];
            *(float4*)a = *(const float4*)&As[cc][ty<<2];
            *(float4*)b = *(const float4*)&Bs[cc][tx<<2];
            #pragma unroll
            for (int i=0;i<4;i++)
                #pragma unroll
                for (int j=0;j<4;j++)
                    acc[i][j] = fmaf(a[i], b[j], acc[i][j]);
        }
        __syncthreads();
    }

    // Epilogue: d = fl(fl(rsq + esq) - 2*dot), argmin with lowest-index tie-break.
    #pragma unroll
    for (int i=0;i<4;i++){
        int row = row0 + (ty<<2) + i;
        float rsq = g_rsq[row];
        unsigned long long key = 0xFFFFFFFFFFFFFFFFull;
        #pragma unroll
        for (int j=0;j<4;j++){
            int k = k0 + (tx<<2) + j;
            float t = rsq + g_esq[k];              // fp32 add (quantizes like reference)
            float d = fmaf(-2.0f, acc[i][j], t);   // == t - 2*dot (2*dot exact)
            unsigned long long kk = ((unsigned long long)fkey(d) << 32) | (unsigned)k;
            key = (kk < key) ? kk : key;
        }
        #pragma unroll
        for (int off=8; off>=1; off>>=1){
            unsigned long long o = __shfl_xor_sync(0xffffffffu, key, off);
            key = (o < key) ? o : key;
        }
        if (tx==0) atomicMin(&g_best[row], key);
    }
}

// Gather winners, upsample (2-tap linear), update f_hat/f_rest, accumulate loss sum.
__global__ void update_kernel(const float* __restrict__ f, const float* __restrict__ emb, int pn){
    __shared__ double sred[256];
    int bn = blockIdx.x;              // 0..B*N-1
    int b = bn >> 4, n = bn & 15;
    int c = threadIdx.x;

    float h;
    if (pn == Nn){
        // identity: h = emb[idx[b][n]]
        int k0 = (int)(g_best[(size_t)b*pn + n] & 0xFFFFFFFFull);
        h = emb[(size_t)k0*Cc + c];
    } else {
        double scale = (double)pn / 16.0;
        double pos = ((double)n + 0.5)*scale - 0.5;
        if (pos < 0.0) pos = 0.0;
        int i0 = (int)floor(pos);
        if (i0 > pn-1) i0 = pn-1;
        double frac = pos - (double)i0;
        int i1 = i0 + 1; if (i1 > pn-1) i1 = pn-1;
        float w0 = (float)(1.0 - frac);
        int k0 = (int)(g_best[(size_t)b*pn + i0] & 0xFFFFFFFFull);
        if (i1 == i0){
            float w = (float)((double)w0 + frac);    // numpy: float32 += float64
            h = w * emb[(size_t)k0*Cc + c];
        } else {
            float w1 = (float)frac;
            int k1 = (int)(g_best[(size_t)b*pn + i1] & 0xFFFFFFFFull);
            h = fmaf(w1, emb[(size_t)k1*Cc + c], w0 * emb[(size_t)k0*Cc + c]);
        }
    }

    size_t idx = (size_t)bn*Cc + c;
    float fh = g_fhat[idx] + h;
    g_fhat[idx] = fh;
    g_frest[idx] = g_frest[idx] - h;
    float t = fh - f[idx];
    sred[c] = (double)t * (double)t;
    __syncthreads();
    for (int s=128;s>0;s>>=1){
        if (c < s) sred[c] += sred[c+s];
        __syncthreads();
    }
    if (c == 0) atomicAdd(&g_loss, sred[0]);
}

__global__ void finalize_kernel(float* __restrict__ out){
    int i = blockIdx.x*blockDim.x + threadIdx.x;
    if (i < Bb*Nn*Cc) out[i] = g_fhat[i];
    if (i == 0){
        double S = g_loss / (double)(Bb*Nn*Cc);   // sum over stages of per-stage means
        out[Bb*Nn*Cc]     = (float)(0.25 * S / 16.0);   // commit
        out[Bb*Nn*Cc + 1] = (float)(S / 16.0);          // qlat
    }
}

extern "C" void kernel_launch(void* const* d_in, const int* in_sizes, int n_in,
                              void* d_out, int out_size){
    const float* f   = (const float*)d_in[0];
    const float* emb = (const float*)d_in[1];
    float* out = (float*)d_out;

    init_kernel<<<(Bb*Nn*Cc + 255)/256, 256>>>(f);
    esq_kernel<<<(Kk + 255)/256, 256>>>(emb);

    for (int pn=1; pn<=Nn; pn++){
        int M = Bb*pn;
        pool_kernel<<<M, 256>>>(pn);
        rsq_kernel<<<(M + 255)/256, 256>>>(M);
        dim3 grid(Kk/64, M/64);
        gemm_argmin_kernel<<<grid, 256>>>(emb);
        update_kernel<<<Bb*Nn, 256>>>(f, emb, pn);
    }
    finalize_kernel<<<(Bb*Nn*Cc + 255)/256, 256>>>(out);
}